// round 17
// baseline (speedup 1.0000x reference)
#include <cuda_runtime.h>
#include <math.h>

// Problem constants
#define BB 4
#define TT 2048
#define DD 512
#define HH 8
#define DH 64
#define LL 2
#define GG 64      // gate blocks per batch == partial rows per batch
#define EPSF 1e-5f
#define NMID 32    // mid blocks

// Scratch (no device allocation allowed -> __device__ globals)
__device__ float g_part[BB][GG][DD];   // per-block partial sums of rstd*(x-mean)
__device__ float g_M[BB][HH][DD];      // folded per-head D-vectors
__device__ float g_S[BB][HH];          // sum_d M'
__device__ float g_bias[BB][HH];       // sum_d ln_b * M
__device__ float g_valid[2][BB];       // clipped valid counts: [0]=vid, [1]=aud
__device__ int   g_all[2][BB];         // all-masked flags
__device__ int   g_flag[4];            // per-stage mid-done counters (32 each)
__device__ int   g_emit[4][BB];        // per-stage partial-emit counters (64 each)

// ---------------------------------------------------------------------------
// Pairwise-packed warp all-reduce: full-warp sums of BOTH a and b in all
// lanes, 6 shfl. hi = (lane & 16).
// ---------------------------------------------------------------------------
__device__ __forceinline__ void wsum2(float a, float b, float& sa, float& sb,
                                      unsigned hi) {
    float t = __shfl_xor_sync(0xffffffffu, hi ? a : b, 16);
    float r = (hi ? b : a) + t;
    r += __shfl_xor_sync(0xffffffffu, r, 8);
    r += __shfl_xor_sync(0xffffffffu, r, 4);
    r += __shfl_xor_sync(0xffffffffu, r, 2);
    r += __shfl_xor_sync(0xffffffffu, r, 1);
    float o = __shfl_xor_sync(0xffffffffu, r, 16);
    sa = hi ? o : r;
    sb = hi ? r : o;
}

// Packed variant: low-half lanes get sum(a), high-half sum(b). 5 shfl.
__device__ __forceinline__ float wsum2_packed(float a, float b, unsigned hi) {
    float t = __shfl_xor_sync(0xffffffffu, hi ? a : b, 16);
    float r = (hi ? b : a) + t;
    r += __shfl_xor_sync(0xffffffffu, r, 8);
    r += __shfl_xor_sync(0xffffffffu, r, 4);
    r += __shfl_xor_sync(0xffffffffu, r, 2);
    r += __shfl_xor_sync(0xffffffffu, r, 1);
    return r;
}

// ---------------------------------------------------------------------------
// Init kernel (first graph node): mask stats + zero all sync counters.
// grid 8 blocks x 256 threads.
// ---------------------------------------------------------------------------
__global__ void k_init(const int* __restrict__ vid_kpm,
                       const int* __restrict__ aud_kpm) {
    int m = blockIdx.x >> 2;          // 0 = vid mask, 1 = aud mask
    int b = blockIdx.x & 3;
    int tid = threadIdx.x;
    int warp = tid >> 5, lane = tid & 31;
    if (blockIdx.x == 0) {
        if (tid < 4) g_flag[tid] = 0;
        if (tid >= 4 && tid < 4 + 4 * BB) ((int*)g_emit)[tid - 4] = 0;
    }
    const int* kp = (m == 0 ? vid_kpm : aud_kpm) + (size_t)b * TT;
    int cnt = 0;
#pragma unroll
    for (int i = 0; i < 8; i++) cnt += (kp[tid + i * 256] == 0);
#pragma unroll
    for (int off = 16; off; off >>= 1)
        cnt += __shfl_xor_sync(0xffffffffu, cnt, off);
    __shared__ int csh_i[8];
    if (lane == 0) csh_i[warp] = cnt;
    __syncthreads();
    if (tid == 0) {
        int c = 0;
        for (int w = 0; w < 8; w++) c += csh_i[w];
        g_valid[m][b] = fmaxf((float)c, 1.0f);
        g_all[m][b] = (c == 0) ? 1 : 0;
    }
}

// ---------------------------------------------------------------------------
// Persistent kernel: 288 blocks (32 mid + 256 gate), 256 threads, 2/SM ->
// all co-resident (required: stage-loop deps assume every block is running).
//   gate block (b,blk): initial aud reduce -> emit[0]; then per stage:
//     phase A stats -> wait g_flag[st] -> __ldcg M -> dots/MLP/write ->
//     emit partials -> g_emit[st+1].
//   mid block (b,h): per stage: wait g_emit[st][b]==GG -> fold g_part
//     (__ldcg: stale-L1 hazard across stages) -> M',S,bias -> g_flag[st].
// ---------------------------------------------------------------------------
__global__ void __launch_bounds__(256, 2)
k_persist(const float* __restrict__ x_vid, const float* __restrict__ x_aud,
          float* out_vid, float* out_aud,
          const int* __restrict__ vid_kpm, const int* __restrict__ aud_kpm,
          const float* __restrict__ Wq_vid, const float* __restrict__ Wk_aud,
          const float* __restrict__ Wq_aud, const float* __restrict__ Wk_vid,
          const float* __restrict__ vgW1, const float* __restrict__ vgb1,
          const float* __restrict__ vgW2, const float* __restrict__ vgb2,
          const float* __restrict__ agW1, const float* __restrict__ agb1,
          const float* __restrict__ agW2, const float* __restrict__ agb2,
          const float* __restrict__ vid_g, const float* __restrict__ vid_b,
          const float* __restrict__ aud_g, const float* __restrict__ aud_b) {
    int tid = threadIdx.x;
    int warp = tid >> 5, lane = tid & 31;
    unsigned hi = lane & 16;

    __shared__ float Msh[HH * DD];             // 16 KB; gate: M + staging
    __shared__ float csh[DD];                  // mid: folded c vector
    __shared__ float ksh[DH];
    __shared__ float rs8[8], rb8[8];
    __shared__ float Ssh[HH], Bsh[HH];
    __shared__ float W1sh[128], b1sh[16], W2sh[16];
    __shared__ float b2sh;
    __shared__ int allsh;

    if (blockIdx.x < NMID) {
        // ================= mid block: one (b,h), loops stages =================
        int b = blockIdx.x >> 3, h = blockIdx.x & 7;
#pragma unroll 1
        for (int st = 0; st < 4; st++) {
            int srcm = (st & 1) ? 0 : 1;       // vid stage sources aud mask(1)
            const float* Wq; const float* Wk; const float* lng; const float* lnb;
            {
                int l = st >> 1;
                size_t wofs = (size_t)l * DD * DD;
                if ((st & 1) == 0) { Wq = Wq_vid + wofs; Wk = Wk_aud + wofs;
                                     lng = vid_g + (size_t)l * DD; lnb = vid_b + (size_t)l * DD; }
                else               { Wq = Wq_aud + wofs; Wk = Wk_vid + wofs;
                                     lng = aud_g + (size_t)l * DD; lnb = aud_b + (size_t)l * DD; }
            }
            // wait for all GG partial emissions of this batch
            if (tid == 0) {
                volatile int* ve = &g_emit[st][b];
                while (*ve < GG) __nanosleep(256);
                __threadfence();               // acquire
            }
            __syncthreads();

            float validf = g_valid[srcm][b];
            float cntf = g_all[srcm][b] ? 0.f : validf;

            float a0 = 0.f, a1 = 0.f;
#pragma unroll 8
            for (int g = 0; g < GG; g++) {     // __ldcg: bypass possibly-stale L1
                a0 += __ldcg(&g_part[b][g][tid]);
                a1 += __ldcg(&g_part[b][g][tid + 256]);
            }
            csh[tid]       = lng[tid] * a0 + cntf * lnb[tid];
            csh[tid + 256] = lng[tid + 256] * a1 + cntf * lnb[tid + 256];
            __syncthreads();

            float rowp[8];
#pragma unroll
            for (int jj = 0; jj < 8; jj++) {
                int j = warp * 8 + jj;
                const float* wk = Wk + (size_t)(h * DH + j) * DD;
                float s = 0.f;
#pragma unroll
                for (int k = 0; k < 16; k++) { int d = lane + 32 * k; s += csh[d] * wk[d]; }
                rowp[jj] = s;
            }
#pragma unroll
            for (int p = 0; p < 4; p++) {
                float r = wsum2_packed(rowp[2 * p], rowp[2 * p + 1], hi);
                if (lane == 0)       ksh[warp * 8 + 2 * p]     = r;
                else if (lane == 16) ksh[warp * 8 + 2 * p + 1] = r;
            }
            __syncthreads();

            float m0 = 0.f, m1 = 0.f;
#pragma unroll
            for (int j = 0; j < DH; j++) {
                float kj = ksh[j];
                const float* wq = Wq + (size_t)(h * DH + j) * DD;
                m0 += kj * wq[tid];
                m1 += kj * wq[tid + 256];
            }
            float inv = 0.125f / validf;
            m0 *= inv; m1 *= inv;
            float mp0 = m0 * lng[tid], mp1 = m1 * lng[tid + 256];
            g_M[b][h][tid]       = mp0;
            g_M[b][h][tid + 256] = mp1;

            float r = wsum2_packed(mp0 + mp1,
                                   lnb[tid] * m0 + lnb[tid + 256] * m1, hi);
            if (lane == 0)       rs8[warp] = r;
            else if (lane == 16) rb8[warp] = r;
            __threadfence();
            __syncthreads();
            if (tid == 0) {
                float S = 0.f, Bv = 0.f;
                for (int w = 0; w < 8; w++) { S += rs8[w]; Bv += rb8[w]; }
                g_S[b][h] = S;
                g_bias[b][h] = Bv;
                __threadfence();               // release
                atomicAdd(&g_flag[st], 1);
            }
            __syncthreads();                   // protect csh/ksh reuse next stage
        }
        return;
    }

    // ================= gate block: (b, blk), loops stages =================
    int blkid = blockIdx.x - NMID;
    int b = blkid >> 6, blk = blkid & 63;
    int t0 = blk * 32 + warp * 4;
    int eidx = lane & 15;
    const float4* M4 = (const float4*)&Msh[0];

    // ---- initial reduce: masked LN-sum of x_aud tokens t0..t0+3 ----
    {
        const float4* base = (const float4*)(x_aud + ((size_t)b * TT + t0) * DD);
        float s[4], sq[4];
#pragma unroll
        for (int t = 0; t < 4; t++) { s[t] = 0.f; sq[t] = 0.f; }
#pragma unroll
        for (int k = 0; k < 4; k++) {
#pragma unroll
            for (int t = 0; t < 4; t++) {
                float4 x = base[t * 128 + k * 32 + lane];
                s[t]  += x.x + x.y + x.z + x.w;
                sq[t] += x.x * x.x + x.y * x.y + x.z * x.z + x.w * x.w;
            }
        }
#pragma unroll
        for (int t = 0; t < 4; t++) wsum2(s[t], sq[t], s[t], sq[t], hi);
        float acc[16];
#pragma unroll
        for (int i = 0; i < 16; i++) acc[i] = 0.f;
#pragma unroll
        for (int t = 0; t < 4; t++) {
            if (aud_kpm[(size_t)b * TT + t0 + t]) continue;
            float mean = s[t] * (1.f / DD);
            float var  = sq[t] * (1.f / DD) - mean * mean;
            float rstd = rsqrtf(var + EPSF);
            float sub  = rstd * mean;
#pragma unroll
            for (int k = 0; k < 4; k++) {
                float4 x = base[t * 128 + k * 32 + lane];   // L1 hit
                acc[k * 4 + 0] += rstd * x.x - sub;
                acc[k * 4 + 1] += rstd * x.y - sub;
                acc[k * 4 + 2] += rstd * x.z - sub;
                acc[k * 4 + 3] += rstd * x.w - sub;
            }
        }
#pragma unroll
        for (int k = 0; k < 4; k++)
            *(float4*)&Msh[warp * DD + k * 128 + lane * 4] =
                make_float4(acc[k * 4], acc[k * 4 + 1], acc[k * 4 + 2], acc[k * 4 + 3]);
        __syncthreads();
        float r0 = 0.f, r1 = 0.f;
#pragma unroll
        for (int w = 0; w < 8; w++) {
            r0 += Msh[w * DD + tid];
            r1 += Msh[w * DD + tid + 256];
        }
        g_part[b][blk][tid]       = r0;
        g_part[b][blk][tid + 256] = r1;
        __threadfence();
        __syncthreads();
        if (tid == 0) atomicAdd(&g_emit[0][b], 1);
    }

#pragma unroll 1
    for (int st = 0; st < 4; st++) {
        int srcm = (st & 1) ? 0 : 1;
        int emit = (st < 3);
        const float* xin; float* xo;
        const float* W1; const float* b1; const float* W2; const float* b2;
        const int* ekpm;
        {
            int l = st >> 1;
            if ((st & 1) == 0) {
                xin = (l == 0) ? x_vid : out_vid; xo = out_vid;
                W1 = vgW1 + (size_t)l * 128; b1 = vgb1 + (size_t)l * 16;
                W2 = vgW2 + (size_t)l * 16;  b2 = vgb2 + l;
                ekpm = vid_kpm;
            } else {
                xin = (l == 0) ? x_aud : out_aud; xo = out_aud;
                W1 = agW1 + (size_t)l * 128; b1 = agb1 + (size_t)l * 16;
                W2 = agW2 + (size_t)l * 16;  b2 = agb2 + l;
                ekpm = aud_kpm;
            }
        }
        __syncthreads();                       // Msh free from previous use
        if (tid >= 32 && tid < 160) W1sh[tid - 32] = W1[tid - 32];
        if (tid >= 160 && tid < 176) b1sh[tid - 160] = b1[tid - 160];
        if (tid >= 176 && tid < 192) W2sh[tid - 176] = W2[tid - 176];
        if (tid == 192) b2sh = b2[0];
        if (tid == 193) allsh = g_all[srcm][b];

        const float4* base = (const float4*)(xin + ((size_t)b * TT + t0) * DD);
        float4* obase = (float4*)(xo + ((size_t)b * TT + t0) * DD);

        // ---- phase A: LN stats (overlaps mid) ----
        float s[4], sq[4];
#pragma unroll
        for (int t = 0; t < 4; t++) { s[t] = 0.f; sq[t] = 0.f; }
#pragma unroll
        for (int k = 0; k < 4; k++) {
#pragma unroll
            for (int t = 0; t < 4; t++) {
                float4 x = base[t * 128 + k * 32 + lane];
                s[t]  += x.x + x.y + x.z + x.w;
                sq[t] += x.x * x.x + x.y * x.y + x.z * x.z + x.w * x.w;
            }
        }
#pragma unroll
        for (int t = 0; t < 4; t++) wsum2(s[t], sq[t], s[t], sq[t], hi);

        // ---- wait for mids ----
        if (tid == 0) {
            volatile int* vf = &g_flag[st];
            while (*vf < NMID) __nanosleep(256);
            __threadfence();                   // acquire
        }
        __syncthreads();

        // ---- load M/S/bias (L1-bypass) ----
        {
            const float4* msrc = (const float4*)&g_M[b][0][0];
            float4* mdst = (float4*)&Msh[0];
#pragma unroll
            for (int i = 0; i < 4; i++) mdst[tid + i * 256] = __ldcg(msrc + tid + i * 256);
            if (tid < HH) { Ssh[tid] = __ldcg(&g_S[b][tid]); Bsh[tid] = __ldcg(&g_bias[b][tid]); }
        }
        __syncthreads();

        // ---- phase B: dots (x L1-hot) ----
        float dot[4][8];
#pragma unroll
        for (int t = 0; t < 4; t++)
#pragma unroll
            for (int h = 0; h < 8; h++) dot[t][h] = 0.f;
#pragma unroll
        for (int k = 0; k < 4; k++) {
            float4 xv[4];
#pragma unroll
            for (int t = 0; t < 4; t++) xv[t] = base[t * 128 + k * 32 + lane];
#pragma unroll
            for (int h = 0; h < 8; h++) {
                float4 mv = M4[h * 128 + k * 32 + lane];
#pragma unroll
                for (int t = 0; t < 4; t++) {
                    dot[t][h] += xv[t].x * mv.x + xv[t].y * mv.y
                               + xv[t].z * mv.z + xv[t].w * mv.w;
                }
            }
        }
#pragma unroll
        for (int t = 0; t < 4; t++)
#pragma unroll
            for (int i = 0; i < 4; i++)
                wsum2(dot[t][i], dot[t][i + 4], dot[t][i], dot[t][i + 4], hi);

        // ---- gate MLP (lane-parallel) ----
        float mean[4], var[4], part[4];
#pragma unroll
        for (int t = 0; t < 4; t++) {
            mean[t] = s[t] * (1.f / DD);
            var[t]  = sq[t] * (1.f / DD) - mean[t] * mean[t];
            float rstd = rsqrtf(var[t] + EPSF);
            float a = b1sh[eidx];
#pragma unroll
            for (int h = 0; h < 8; h++) {
                float rel = rstd * (dot[t][h] - mean[t] * Ssh[h]) + Bsh[h];
                a += rel * W1sh[eidx * 8 + h];
            }
            part[t] = fmaxf(a, 0.f) * W2sh[eidx];
        }
        wsum2(part[0], part[1], part[0], part[1], hi);
        wsum2(part[2], part[3], part[2], part[3], hi);

        float factor[4], rf[4], sub2[4];
#pragma unroll
        for (int t = 0; t < 4; t++) {
            float gacc = b2sh + 0.5f * part[t];
            float gate = 1.f / (1.f + expf(-gacc));
            if (allsh) gate = 0.f;
            factor[t] = 1.f + gate;
            float rstd2 = rsqrtf(factor[t] * factor[t] * var[t] + EPSF);
            rf[t]   = rstd2 * factor[t];
            sub2[t] = rf[t] * mean[t];
        }

        // ---- phase C: write out + emit partials ----
        float acc[16];
#pragma unroll
        for (int i = 0; i < 16; i++) acc[i] = 0.f;
#pragma unroll
        for (int t = 0; t < 4; t++) {
            int keep = emit ? (ekpm[(size_t)b * TT + t0 + t] == 0) : 0;
#pragma unroll
            for (int k = 0; k < 4; k++) {
                float4 x = base[t * 128 + k * 32 + lane];
                float4 o;
                o.x = x.x * factor[t]; o.y = x.y * factor[t];
                o.z = x.z * factor[t]; o.w = x.w * factor[t];
                obase[t * 128 + k * 32 + lane] = o;
                if (keep) {
                    acc[k * 4 + 0] += rf[t] * x.x - sub2[t];
                    acc[k * 4 + 1] += rf[t] * x.y - sub2[t];
                    acc[k * 4 + 2] += rf[t] * x.z - sub2[t];
                    acc[k * 4 + 3] += rf[t] * x.w - sub2[t];
                }
            }
        }

        if (emit) {
            __syncthreads();   // Msh reads done; safe vs mid (flag passed)
#pragma unroll
            for (int k = 0; k < 4; k++)
                *(float4*)&Msh[warp * DD + k * 128 + lane * 4] =
                    make_float4(acc[k * 4], acc[k * 4 + 1], acc[k * 4 + 2], acc[k * 4 + 3]);
            __syncthreads();
            float r0 = 0.f, r1 = 0.f;
#pragma unroll
            for (int w = 0; w < 8; w++) {
                r0 += Msh[w * DD + tid];
                r1 += Msh[w * DD + tid + 256];
            }
            g_part[b][blk][tid]       = r0;
            g_part[b][blk][tid + 256] = r1;
            __threadfence();
            __syncthreads();
            if (tid == 0) atomicAdd(&g_emit[st + 1][b], 1);
        }
    }
}

// ---------------------------------------------------------------------------
extern "C" void kernel_launch(void* const* d_in, const int* in_sizes, int n_in,
                              void* d_out, int out_size) {
    (void)in_sizes; (void)n_in; (void)out_size;
    const float* x_vid = (const float*)d_in[0];
    const float* x_aud = (const float*)d_in[1];
    const int* vid_kpm = (const int*)d_in[2];
    const int* aud_kpm = (const int*)d_in[3];
    const float* Wq_vid = (const float*)d_in[4];
    const float* Wk_aud = (const float*)d_in[5];
    const float* Wq_aud = (const float*)d_in[6];
    const float* Wk_vid = (const float*)d_in[7];
    const float* vgW1 = (const float*)d_in[8];
    const float* vgb1 = (const float*)d_in[9];
    const float* vgW2 = (const float*)d_in[10];
    const float* vgb2 = (const float*)d_in[11];
    const float* agW1 = (const float*)d_in[12];
    const float* agb1 = (const float*)d_in[13];
    const float* agW2 = (const float*)d_in[14];
    const float* agb2 = (const float*)d_in[15];
    const float* vid_g = (const float*)d_in[16];
    const float* vid_b = (const float*)d_in[17];
    const float* aud_g = (const float*)d_in[18];
    const float* aud_b = (const float*)d_in[19];

    const size_t N = (size_t)BB * TT * DD;
    float* out_vid = (float*)d_out;
    float* out_aud = out_vid + N;

    k_init<<<8, 256>>>(vid_kpm, aud_kpm);
    k_persist<<<NMID + GG * BB, 256>>>(x_vid, x_aud, out_vid, out_aud,
                                       vid_kpm, aud_kpm,
                                       Wq_vid, Wk_aud, Wq_aud, Wk_vid,
                                       vgW1, vgb1, vgW2, vgb2,
                                       agW1, agb1, agW2, agb2,
                                       vid_g, vid_b, aud_g, aud_b);
}